// round 15
// baseline (speedup 1.0000x reference)
#include <cuda_runtime.h>

#define NTOK 32768
#define NH 32
#define NCH 9                 // float4 feature chunks per token (36 floats)
#define SLICE (NCH * NTOK)

// Feature slices: 0..9 obs inputs, 10..19 obs outputs, 20..21 pred ping-pong.
__device__ float4 g_ftr[22 * SLICE];

// Precomputed folded weights
__device__ float g_M[36 * 36];     // (Wq^T Wk)/sqrt(34), [i][j], zero-padded
__device__ float g_kb[36];
__device__ float g_qb[36];
__device__ float g_cc[1];
__device__ float g_cv[36][32];     // CV[j][k]
__device__ float g_cb2[32];
__device__ float g_f2h[32][32];    // [i][k] = f2w[k][i] - colmean
__device__ float g_bh[32];
__device__ int   g_flag[128];      // per-block step counters (pred)

typedef unsigned long long u64;

__device__ __forceinline__ u64 pack2(float lo, float hi) {
    u64 r; asm("mov.b64 %0, {%1, %2};" : "=l"(r) : "f"(lo), "f"(hi)); return r;
}
__device__ __forceinline__ void unpack2(u64 v, float& lo, float& hi) {
    asm("mov.b64 {%0, %1}, %2;" : "=f"(lo), "=f"(hi) : "l"(v));
}
__device__ __forceinline__ u64 ffma2(u64 a, u64 b, u64 c) {
    u64 d; asm("fma.rn.f32x2 %0, %1, %2, %3;" : "=l"(d) : "l"(a), "l"(b), "l"(c)); return d;
}
__device__ __forceinline__ u64 fadd2(u64 a, u64 b) {
    u64 d; asm("add.rn.f32x2 %0, %1, %2;" : "=l"(d) : "l"(a), "l"(b)); return d;
}
__device__ __forceinline__ u64 fmul2(u64 a, u64 b) {
    u64 d; asm("mul.rn.f32x2 %0, %1, %2;" : "=l"(d) : "l"(a), "l"(b)); return d;
}

// ---------------------------------------------------------------------------
__global__ void __launch_bounds__(256) precomp_kernel(
    const float* __restrict__ ipw, const float* __restrict__ ipb,
    const float* __restrict__ opw, const float* __restrict__ opb,
    const float* __restrict__ saw, const float* __restrict__ sab,
    const float* __restrict__ f2w, const float* __restrict__ f2b)
{
    __shared__ float sCW[32][34];
    int tid = threadIdx.x;
    const float SC = 0.17149858514250882f;  // 1/sqrt(34)

    for (int idx = tid; idx < 36 * 36; idx += 256) {
        int i = idx / 36, j = idx % 36;
        float acc = 0.f;
        if (i < 34 && j < 34)
            for (int e = 0; e < 34; e++) acc += ipw[e * 34 + i] * ipw[(34 + e) * 34 + j];
        g_M[idx] = acc * SC;
    }
    for (int j = tid; j < 36; j += 256) {
        float a = 0.f, b = 0.f;
        if (j < 34)
            for (int e = 0; e < 34; e++) {
                a += ipb[e] * ipw[(34 + e) * 34 + j];
                b += ipw[e * 34 + j] * ipb[34 + e];
            }
        g_kb[j] = a * SC;
        g_qb[j] = b * SC;
    }
    if (tid == 0) {
        float c = 0.f;
        for (int e = 0; e < 34; e++) c += ipb[e] * ipb[34 + e];
        g_cc[0] = c * SC;
    }
    for (int idx = tid; idx < 32 * 34; idx += 256) {
        int k = idx / 34, i = idx % 34;
        float acc = 0.f;
        for (int t = 0; t < 34; t++) acc += saw[k * 34 + t] * opw[t * 34 + i];
        sCW[k][i] = acc;
    }
    __syncthreads();
    for (int idx = tid; idx < 36 * 32; idx += 256) {
        int j = idx / 32, k = idx % 32;
        float acc = 0.f;
        if (j < 34)
            for (int i = 0; i < 34; i++) acc += sCW[k][i] * ipw[(68 + i) * 34 + j];
        g_cv[j][k] = acc;
    }
    for (int k = tid; k < 32; k += 256) {
        float acc = sab[k];
        for (int t = 0; t < 34; t++) acc += saw[k * 34 + t] * opb[t];
        for (int i = 0; i < 34; i++) acc += sCW[k][i] * ipb[68 + i];
        g_cb2[k] = acc;
    }
    for (int idx = tid; idx < 32 * 32; idx += 256) {
        int i = idx / 32, k = idx % 32;
        float mu = 0.f;
        for (int kk = 0; kk < 32; kk++) mu += f2w[kk * 32 + i];
        g_f2h[i][k] = f2w[k * 32 + i] - mu * (1.f / 32.f);
    }
    for (int k = tid; k < 32; k += 256) {
        float mb = 0.f;
        for (int kk = 0; kk < 32; kk++) mb += f2b[kk];
        g_bh[k] = f2b[k] - mb * (1.f / 32.f);
    }
}

// ---------------------------------------------------------------------------
__global__ void __launch_bounds__(128) prep_kernel(const float* __restrict__ x)
{
    int tid = threadIdx.x;
    int n = blockIdx.x * 128 + tid;
    int z = blockIdx.z;
    const float4* h4 = reinterpret_cast<const float4*>(x + ((size_t)z * NTOK + n) * NH);
    float4* o = g_ftr + (size_t)z * SLICE + n;
#pragma unroll
    for (int c = 0; c < 8; c++) o[(size_t)c * NTOK] = h4[c];
    int p = n & 4095;
    float4 lab;
    lab.x = (float)(p >> 6) * (1.f / 64.f);
    lab.y = (float)(p & 63) * (1.f / 64.f);
    lab.z = 0.f; lab.w = 0.f;
    o[(size_t)8 * NTOK] = lab;
    if (z == 0 && blockIdx.x == 0) g_flag[tid] = 0;   // reset pred flags (128)
}

// ---------------------------------------------------------------------------
struct __align__(16) SW {
    float M[36][36];
    float CV[36][32];
    float F2[32][32];
    float KB[36], QB[36];
    float CB2[32], BH[32], G[32], BB[32];
    float CC;
};

template<int NT>
__device__ __forceinline__ void stage_weights(SW& s, int tid,
        const float* __restrict__ lng, const float* __restrict__ lnb)
{
    for (int idx = tid; idx < 36 * 36; idx += NT) s.M[idx / 36][idx % 36] = g_M[idx];
    for (int idx = tid; idx < 36 * 32; idx += NT) s.CV[idx / 32][idx % 32] = g_cv[idx / 32][idx % 32];
    for (int idx = tid; idx < 32 * 32; idx += NT) s.F2[idx / 32][idx % 32] = g_f2h[idx / 32][idx % 32];
    if (tid < 36) { s.KB[tid] = g_kb[tid]; s.QB[tid] = g_qb[tid]; }
    if (tid < 32) {
        s.CB2[tid] = g_cb2[tid]; s.BH[tid] = g_bh[tid];
        s.G[tid] = lng[tid];     s.BB[tid] = lnb[tid];
    }
    if (tid == 0) s.CC = g_cc[0];
}

// ---------------------------------------------------------------------------
// One token's full step: single-pass no-max softmax, packed f32x2.
// ---------------------------------------------------------------------------
__device__ __forceinline__ void do_token(const SW& s,
    const float4* __restrict__ fin, float4* __restrict__ fout,
    float* __restrict__ orow, int n, const int* jt, int row, int col)
{
    // pass A: a = M^T f4 + kb ; c4 = qb.f4 + cc
    float f4f[36];
#pragma unroll
    for (int c = 0; c < 9; c++) {
        float4 v = fin[(size_t)c * NTOK + jt[4]];
        f4f[4 * c + 0] = v.x; f4f[4 * c + 1] = v.y;
        f4f[4 * c + 2] = v.z; f4f[4 * c + 3] = v.w;
    }
    float c4 = s.CC;
#pragma unroll
    for (int i = 0; i < 34; i++) c4 += f4f[i] * s.QB[i];

    u64 a[18];
#pragma unroll
    for (int t = 0; t < 9; t++) {
        ulonglong2 kb = *reinterpret_cast<const ulonglong2*>(&s.KB[4 * t]);
        a[2 * t] = kb.x; a[2 * t + 1] = kb.y;
    }
#pragma unroll
    for (int i = 0; i < 34; i++) {
        u64 fp = pack2(f4f[i], f4f[i]);
#pragma unroll
        for (int t = 0; t < 9; t++) {
            ulonglong2 w = *reinterpret_cast<const ulonglong2*>(&s.M[i][4 * t]);
            a[2 * t]     = ffma2(fp, w.x, a[2 * t]);
            a[2 * t + 1] = ffma2(fp, w.y, a[2 * t + 1]);
        }
    }

    // single pass: score -> exp (no max; scores O(1)) -> fbar accumulate
    u64 fb[18];
#pragma unroll
    for (int t = 0; t < 18; t++) fb[t] = 0ull;
    float l = 0.f;
#pragma unroll
    for (int sx = 0; sx < 9; sx++) {
        const float4* fp4 = fin + jt[sx];
        u64 fs[18];
#pragma unroll
        for (int c = 0; c < 9; c++) {
            ulonglong2 v = *reinterpret_cast<const ulonglong2*>(&fp4[(size_t)c * NTOK]);
            fs[2 * c] = v.x; fs[2 * c + 1] = v.y;
        }
        u64 d0 = 0ull, d1 = 0ull;
#pragma unroll
        for (int t = 0; t < 9; t++) {
            d0 = ffma2(a[2 * t], fs[2 * t], d0);
            d1 = ffma2(a[2 * t + 1], fs[2 * t + 1], d1);
        }
        float x0, x1, x2, x3;
        unpack2(d0, x0, x1); unpack2(d1, x2, x3);
        float e = __expf((x0 + x1) + (x2 + x3) + c4);
        l += e;
        u64 ep = pack2(e, e);
#pragma unroll
        for (int t = 0; t < 18; t++)
            fb[t] = ffma2(ep, fs[t], fb[t]);
    }
    float rl = 1.f / l;
    u64 rlp = pack2(rl, rl);

    // z = h + CV @ fbar + cb2
    u64 zacc[16];
#pragma unroll
    for (int t = 0; t < 8; t++) {
        ulonglong2 bb = *reinterpret_cast<const ulonglong2*>(&s.CB2[4 * t]);
        zacc[2 * t] = bb.x; zacc[2 * t + 1] = bb.y;
    }
#pragma unroll
    for (int c = 0; c < 8; c++) {
        ulonglong2 hv = *reinterpret_cast<const ulonglong2*>(&fin[(size_t)c * NTOK + n]);
        zacc[2 * c]     = fadd2(zacc[2 * c], hv.x);
        zacc[2 * c + 1] = fadd2(zacc[2 * c + 1], hv.y);
    }
#pragma unroll
    for (int t = 0; t < 17; t++) {   // j = 2t, 2t+1 (0..33)
        u64 fbn = fmul2(fb[t], rlp);
        float f0, f1; unpack2(fbn, f0, f1);
        u64 fp0 = pack2(f0, f0), fp1 = pack2(f1, f1);
#pragma unroll
        for (int k = 0; k < 8; k++) {
            ulonglong2 w = *reinterpret_cast<const ulonglong2*>(&s.CV[2 * t][4 * k]);
            zacc[2 * k]     = ffma2(fp0, w.x, zacc[2 * k]);
            zacc[2 * k + 1] = ffma2(fp0, w.y, zacc[2 * k + 1]);
        }
#pragma unroll
        for (int k = 0; k < 8; k++) {
            ulonglong2 w = *reinterpret_cast<const ulonglong2*>(&s.CV[2 * t + 1][4 * k]);
            zacc[2 * k]     = ffma2(fp1, w.x, zacc[2 * k]);
            zacc[2 * k + 1] = ffma2(fp1, w.y, zacc[2 * k + 1]);
        }
    }

    // v = F2h @ z + bh
    u64 vacc[16];
#pragma unroll
    for (int t = 0; t < 8; t++) {
        ulonglong2 bb = *reinterpret_cast<const ulonglong2*>(&s.BH[4 * t]);
        vacc[2 * t] = bb.x; vacc[2 * t + 1] = bb.y;
    }
#pragma unroll
    for (int t = 0; t < 16; t++) {   // i = 2t, 2t+1
        float z0, z1; unpack2(zacc[t], z0, z1);
        u64 zp0 = pack2(z0, z0), zp1 = pack2(z1, z1);
#pragma unroll
        for (int k = 0; k < 8; k++) {
            ulonglong2 w = *reinterpret_cast<const ulonglong2*>(&s.F2[2 * t][4 * k]);
            vacc[2 * k]     = ffma2(zp0, w.x, vacc[2 * k]);
            vacc[2 * k + 1] = ffma2(zp0, w.y, vacc[2 * k + 1]);
        }
#pragma unroll
        for (int k = 0; k < 8; k++) {
            ulonglong2 w = *reinterpret_cast<const ulonglong2*>(&s.F2[2 * t + 1][4 * k]);
            vacc[2 * k]     = ffma2(zp1, w.x, vacc[2 * k]);
            vacc[2 * k + 1] = ffma2(zp1, w.y, vacc[2 * k + 1]);
        }
    }

    // layernorm (mean folded out): var = sum v^2, packed
    u64 varp = 0ull;
#pragma unroll
    for (int t = 0; t < 16; t++) varp = ffma2(vacc[t], vacc[t], varp);
    float v0, v1; unpack2(varp, v0, v1);
    float r = rsqrtf((v0 + v1) * (1.f / 32.f) + 1e-5f);
    u64 rp = pack2(r, r);

    float4* o4 = reinterpret_cast<float4*>(orow);
#pragma unroll
    for (int c = 0; c < 8; c++) {
        u64 y0 = ffma2(fmul2(vacc[2 * c], rp),
                       *reinterpret_cast<const u64*>(&s.G[4 * c]),
                       *reinterpret_cast<const u64*>(&s.BB[4 * c]));
        u64 y1 = ffma2(fmul2(vacc[2 * c + 1], rp),
                       *reinterpret_cast<const u64*>(&s.G[4 * c + 2]),
                       *reinterpret_cast<const u64*>(&s.BB[4 * c + 2]));
        ulonglong2 y; y.x = y0; y.y = y1;
        float4 yf = *reinterpret_cast<float4*>(&y);
        o4[c] = yf;
        fout[(size_t)c * NTOK + n] = yf;
    }
    float4 lab;
    lab.x = (float)row * (1.f / 64.f);
    lab.y = (float)col * (1.f / 64.f);
    lab.z = 0.f; lab.w = 0.f;
    fout[(size_t)8 * NTOK + n] = lab;
}

// ---------------------------------------------------------------------------
// Observation: 10 independent steps, batched over grid.z.
// ---------------------------------------------------------------------------
__global__ void __launch_bounds__(128) obs_kernel(
    float* __restrict__ out,
    const float* __restrict__ lng, const float* __restrict__ lnb)
{
    __shared__ SW s;
    int tid = threadIdx.x;
    stage_weights<128>(s, tid, lng, lnb);
    __syncthreads();

    int z = blockIdx.z;
    const float4* fin = g_ftr + (size_t)z * SLICE;
    float4* fout      = g_ftr + (size_t)(10 + z) * SLICE;

    int n = blockIdx.x * 128 + tid;
    int p = n & 4095;
    int row = p >> 6, col = p & 63;
    int rs = row + (row == 0) - (row == 63);
    int cs = col + (col == 0) - (col == 63);
    int jb = (n >> 12) * 4096;
    int jt[9];
#pragma unroll
    for (int sx = 0; sx < 9; sx++)
        jt[sx] = jb + (rs + sx / 3 - 1) * 64 + (cs + sx % 3 - 1);

    do_token(s, fin, fout, out + ((size_t)z * NTOK + n) * NH, n, jt, row, col);
}

// ---------------------------------------------------------------------------
// Prediction: persistent kernel, 50 sequential steps, one launch.
// 128 blocks x 256 threads: one block per SM, uniform load, all co-resident.
// Block b depends only on blocks b+-1 within its batch (pos = b & 15).
// ---------------------------------------------------------------------------
__global__ void __launch_bounds__(256) pred_kernel(
    float* __restrict__ out,
    const float* __restrict__ lng, const float* __restrict__ lnb)
{
    __shared__ SW s;
    int tid = threadIdx.x;
    stage_weights<256>(s, tid, lng, lnb);
    __syncthreads();

    int b = blockIdx.x;
    int pos = b & 15;                 // block index within its batch (16 blocks/batch)
    int n = b * 256 + tid;
    int p = n & 4095;
    int row = p >> 6, col = p & 63;
    int rs = row + (row == 0) - (row == 63);
    int cs = col + (col == 0) - (col == 63);
    int jb = (n >> 12) * 4096;
    int jt[9];
#pragma unroll
    for (int sx = 0; sx < 9; sx++)
        jt[sx] = jb + (rs + sx / 3 - 1) * 64 + (cs + sx % 3 - 1);

    for (int i = 0; i < 50; i++) {
        const float4* fin = g_ftr + (size_t)(i == 0 ? 19 : 20 + ((i - 1) & 1)) * SLICE;
        float4* fout      = g_ftr + (size_t)(20 + (i & 1)) * SLICE;
        float* orow       = out + ((size_t)(10 + i) * NTOK + n) * NH;

        do_token(s, fin, fout, orow, n, jt, row, col);

        // release all my stores gpu-wide, then publish progress and wait on
        // the two neighbor strips (parallel pollers in different warps)
        __threadfence();
        __syncthreads();
        if (tid == 0)  atomicExch(&g_flag[b], i + 1);
        if (tid == 0 && pos > 0)
            while (atomicAdd(&g_flag[b - 1], 0) <= i) { __nanosleep(20); }
        if (tid == 32 && pos < 15)
            while (atomicAdd(&g_flag[b + 1], 0) <= i) { __nanosleep(20); }
        __syncthreads();
    }
}

// ---------------------------------------------------------------------------
extern "C" void kernel_launch(void* const* d_in, const int* in_sizes, int n_in,
                              void* d_out, int out_size)
{
    const float* x   = (const float*)d_in[0];
    const float* ipw = (const float*)d_in[1];
    const float* ipb = (const float*)d_in[2];
    const float* opw = (const float*)d_in[3];
    const float* opb = (const float*)d_in[4];
    const float* saw = (const float*)d_in[5];
    const float* sab = (const float*)d_in[6];
    const float* f2w = (const float*)d_in[7];
    const float* f2b = (const float*)d_in[8];
    const float* lng = (const float*)d_in[9];
    const float* lnb = (const float*)d_in[10];
    float* out = (float*)d_out;

    precomp_kernel<<<1, 256>>>(ipw, ipb, opw, opb, saw, sab, f2w, f2b);

    prep_kernel<<<dim3(NTOK / 128, 1, 10), 128>>>(x);

    // Observation: slices 0..9 -> 10..19, output rows 0..9
    obs_kernel<<<dim3(NTOK / 128, 1, 10), 128>>>(out, lng, lnb);

    // Prediction: one persistent launch, 50 sequential steps
    pred_kernel<<<dim3(128, 1, 1), 256>>>(out, lng, lnb);
}

// round 17
// speedup vs baseline: 1.0321x; 1.0321x over previous
#include <cuda_runtime.h>

#define NTOK 32768
#define NH 32
#define NCH 9                 // float4 feature chunks per token (36 floats)
#define SLICE (NCH * NTOK)

// Feature slices: 0..9 obs inputs, 10..19 obs outputs, 20..21 pred ping-pong.
__device__ float4 g_ftr[22 * SLICE];

// Precomputed folded weights
__device__ float g_M[36 * 36];     // (Wq^T Wk)/sqrt(34), [i][j], zero-padded
__device__ float g_kb[36];
__device__ float g_qb[36];
__device__ float g_cc[1];
__device__ float g_cv[36][32];     // CV[j][k]
__device__ float g_cb2[32];
__device__ float g_f2h[32][32];    // [i][k] = f2w[k][i] - colmean
__device__ float g_bh[32];
__device__ int   g_flag[256];      // per-block step counters (pred)

typedef unsigned long long u64;

__device__ __forceinline__ u64 pack2(float lo, float hi) {
    u64 r; asm("mov.b64 %0, {%1, %2};" : "=l"(r) : "f"(lo), "f"(hi)); return r;
}
__device__ __forceinline__ void unpack2(u64 v, float& lo, float& hi) {
    asm("mov.b64 {%0, %1}, %2;" : "=f"(lo), "=f"(hi) : "l"(v));
}
__device__ __forceinline__ u64 ffma2(u64 a, u64 b, u64 c) {
    u64 d; asm("fma.rn.f32x2 %0, %1, %2, %3;" : "=l"(d) : "l"(a), "l"(b), "l"(c)); return d;
}
__device__ __forceinline__ u64 fadd2(u64 a, u64 b) {
    u64 d; asm("add.rn.f32x2 %0, %1, %2;" : "=l"(d) : "l"(a), "l"(b)); return d;
}
__device__ __forceinline__ u64 fmul2(u64 a, u64 b) {
    u64 d; asm("mul.rn.f32x2 %0, %1, %2;" : "=l"(d) : "l"(a), "l"(b)); return d;
}

// ---------------------------------------------------------------------------
__global__ void __launch_bounds__(256) precomp_kernel(
    const float* __restrict__ ipw, const float* __restrict__ ipb,
    const float* __restrict__ opw, const float* __restrict__ opb,
    const float* __restrict__ saw, const float* __restrict__ sab,
    const float* __restrict__ f2w, const float* __restrict__ f2b)
{
    __shared__ float sCW[32][34];
    int tid = threadIdx.x;
    const float SC = 0.17149858514250882f;  // 1/sqrt(34)

    for (int idx = tid; idx < 36 * 36; idx += 256) {
        int i = idx / 36, j = idx % 36;
        float acc = 0.f;
        if (i < 34 && j < 34)
            for (int e = 0; e < 34; e++) acc += ipw[e * 34 + i] * ipw[(34 + e) * 34 + j];
        g_M[idx] = acc * SC;
    }
    for (int j = tid; j < 36; j += 256) {
        float a = 0.f, b = 0.f;
        if (j < 34)
            for (int e = 0; e < 34; e++) {
                a += ipb[e] * ipw[(34 + e) * 34 + j];
                b += ipw[e * 34 + j] * ipb[34 + e];
            }
        g_kb[j] = a * SC;
        g_qb[j] = b * SC;
    }
    if (tid == 0) {
        float c = 0.f;
        for (int e = 0; e < 34; e++) c += ipb[e] * ipb[34 + e];
        g_cc[0] = c * SC;
    }
    for (int idx = tid; idx < 32 * 34; idx += 256) {
        int k = idx / 34, i = idx % 34;
        float acc = 0.f;
        for (int t = 0; t < 34; t++) acc += saw[k * 34 + t] * opw[t * 34 + i];
        sCW[k][i] = acc;
    }
    __syncthreads();
    for (int idx = tid; idx < 36 * 32; idx += 256) {
        int j = idx / 32, k = idx % 32;
        float acc = 0.f;
        if (j < 34)
            for (int i = 0; i < 34; i++) acc += sCW[k][i] * ipw[(68 + i) * 34 + j];
        g_cv[j][k] = acc;
    }
    for (int k = tid; k < 32; k += 256) {
        float acc = sab[k];
        for (int t = 0; t < 34; t++) acc += saw[k * 34 + t] * opb[t];
        for (int i = 0; i < 34; i++) acc += sCW[k][i] * ipb[68 + i];
        g_cb2[k] = acc;
    }
    for (int idx = tid; idx < 32 * 32; idx += 256) {
        int i = idx / 32, k = idx % 32;
        float mu = 0.f;
        for (int kk = 0; kk < 32; kk++) mu += f2w[kk * 32 + i];
        g_f2h[i][k] = f2w[k * 32 + i] - mu * (1.f / 32.f);
    }
    for (int k = tid; k < 32; k += 256) {
        float mb = 0.f;
        for (int kk = 0; kk < 32; kk++) mb += f2b[kk];
        g_bh[k] = f2b[k] - mb * (1.f / 32.f);
    }
}

// ---------------------------------------------------------------------------
__global__ void __launch_bounds__(128) prep_kernel(const float* __restrict__ x)
{
    int tid = threadIdx.x;
    int n = blockIdx.x * 128 + tid;
    int z = blockIdx.z;
    const float4* h4 = reinterpret_cast<const float4*>(x + ((size_t)z * NTOK + n) * NH);
    float4* o = g_ftr + (size_t)z * SLICE + n;
#pragma unroll
    for (int c = 0; c < 8; c++) o[(size_t)c * NTOK] = h4[c];
    int p = n & 4095;
    float4 lab;
    lab.x = (float)(p >> 6) * (1.f / 64.f);
    lab.y = (float)(p & 63) * (1.f / 64.f);
    lab.z = 0.f; lab.w = 0.f;
    o[(size_t)8 * NTOK] = lab;
    if (z == 0 && blockIdx.x == 0) {      // reset pred flags (256)
        g_flag[tid] = 0;
        g_flag[tid + 128] = 0;
    }
}

// ---------------------------------------------------------------------------
struct __align__(16) SW {
    float M[36][36];
    float CV[36][32];
    float F2[32][32];
    float KB[36], QB[36];
    float CB2[32], BH[32], G[32], BB[32];
    float CC;
};

template<int NT>
__device__ __forceinline__ void stage_weights(SW& s, int tid,
        const float* __restrict__ lng, const float* __restrict__ lnb)
{
    for (int idx = tid; idx < 36 * 36; idx += NT) s.M[idx / 36][idx % 36] = g_M[idx];
    for (int idx = tid; idx < 36 * 32; idx += NT) s.CV[idx / 32][idx % 32] = g_cv[idx / 32][idx % 32];
    for (int idx = tid; idx < 32 * 32; idx += NT) s.F2[idx / 32][idx % 32] = g_f2h[idx / 32][idx % 32];
    if (tid < 36) { s.KB[tid] = g_kb[tid]; s.QB[tid] = g_qb[tid]; }
    if (tid < 32) {
        s.CB2[tid] = g_cb2[tid]; s.BH[tid] = g_bh[tid];
        s.G[tid] = lng[tid];     s.BB[tid] = lnb[tid];
    }
    if (tid == 0) s.CC = g_cc[0];
}

// ---------------------------------------------------------------------------
// One token's full step: single-pass no-max softmax, packed f32x2.
// ---------------------------------------------------------------------------
__device__ __forceinline__ void do_token(const SW& s,
    const float4* __restrict__ fin, float4* __restrict__ fout,
    float* __restrict__ orow, int n, const int* jt, int row, int col)
{
    // pass A: a = M^T f4 + kb ; c4 = qb.f4 + cc (packed dot)
    float f4f[36];
#pragma unroll
    for (int c = 0; c < 9; c++) {
        float4 v = fin[(size_t)c * NTOK + jt[4]];
        f4f[4 * c + 0] = v.x; f4f[4 * c + 1] = v.y;
        f4f[4 * c + 2] = v.z; f4f[4 * c + 3] = v.w;
    }
    u64 c4p = 0ull;
#pragma unroll
    for (int t = 0; t < 17; t++)
        c4p = ffma2(*reinterpret_cast<const u64*>(&f4f[2 * t]),
                    *reinterpret_cast<const u64*>(&s.QB[2 * t]), c4p);
    float c40, c41; unpack2(c4p, c40, c41);
    float c4 = c40 + c41 + s.CC;

    u64 a[18];
#pragma unroll
    for (int t = 0; t < 9; t++) {
        ulonglong2 kb = *reinterpret_cast<const ulonglong2*>(&s.KB[4 * t]);
        a[2 * t] = kb.x; a[2 * t + 1] = kb.y;
    }
#pragma unroll
    for (int i = 0; i < 34; i++) {
        u64 fp = pack2(f4f[i], f4f[i]);
#pragma unroll
        for (int t = 0; t < 9; t++) {
            ulonglong2 w = *reinterpret_cast<const ulonglong2*>(&s.M[i][4 * t]);
            a[2 * t]     = ffma2(fp, w.x, a[2 * t]);
            a[2 * t + 1] = ffma2(fp, w.y, a[2 * t + 1]);
        }
    }

    // single pass: score -> exp (no max; scores O(1)) -> fbar accumulate
    u64 fb[18];
#pragma unroll
    for (int t = 0; t < 18; t++) fb[t] = 0ull;
    float l = 0.f;
#pragma unroll
    for (int sx = 0; sx < 9; sx++) {
        const float4* fp4 = fin + jt[sx];
        u64 fs[18];
#pragma unroll
        for (int c = 0; c < 9; c++) {
            ulonglong2 v = *reinterpret_cast<const ulonglong2*>(&fp4[(size_t)c * NTOK]);
            fs[2 * c] = v.x; fs[2 * c + 1] = v.y;
        }
        u64 d0 = 0ull, d1 = 0ull;
#pragma unroll
        for (int t = 0; t < 9; t++) {
            d0 = ffma2(a[2 * t], fs[2 * t], d0);
            d1 = ffma2(a[2 * t + 1], fs[2 * t + 1], d1);
        }
        float x0, x1, x2, x3;
        unpack2(d0, x0, x1); unpack2(d1, x2, x3);
        float e = __expf((x0 + x1) + (x2 + x3) + c4);
        l += e;
        u64 ep = pack2(e, e);
#pragma unroll
        for (int t = 0; t < 18; t++)
            fb[t] = ffma2(ep, fs[t], fb[t]);
    }
    float rl = 1.f / l;
    u64 rlp = pack2(rl, rl);

    // z = h + CV @ fbar + cb2
    u64 zacc[16];
#pragma unroll
    for (int t = 0; t < 8; t++) {
        ulonglong2 bb = *reinterpret_cast<const ulonglong2*>(&s.CB2[4 * t]);
        zacc[2 * t] = bb.x; zacc[2 * t + 1] = bb.y;
    }
#pragma unroll
    for (int c = 0; c < 8; c++) {
        ulonglong2 hv = *reinterpret_cast<const ulonglong2*>(&fin[(size_t)c * NTOK + n]);
        zacc[2 * c]     = fadd2(zacc[2 * c], hv.x);
        zacc[2 * c + 1] = fadd2(zacc[2 * c + 1], hv.y);
    }
#pragma unroll
    for (int t = 0; t < 17; t++) {   // j = 2t, 2t+1 (0..33)
        u64 fbn = fmul2(fb[t], rlp);
        float f0, f1; unpack2(fbn, f0, f1);
        u64 fp0 = pack2(f0, f0), fp1 = pack2(f1, f1);
#pragma unroll
        for (int k = 0; k < 8; k++) {
            ulonglong2 w = *reinterpret_cast<const ulonglong2*>(&s.CV[2 * t][4 * k]);
            zacc[2 * k]     = ffma2(fp0, w.x, zacc[2 * k]);
            zacc[2 * k + 1] = ffma2(fp0, w.y, zacc[2 * k + 1]);
        }
#pragma unroll
        for (int k = 0; k < 8; k++) {
            ulonglong2 w = *reinterpret_cast<const ulonglong2*>(&s.CV[2 * t + 1][4 * k]);
            zacc[2 * k]     = ffma2(fp1, w.x, zacc[2 * k]);
            zacc[2 * k + 1] = ffma2(fp1, w.y, zacc[2 * k + 1]);
        }
    }

    // v = F2h @ z + bh
    u64 vacc[16];
#pragma unroll
    for (int t = 0; t < 8; t++) {
        ulonglong2 bb = *reinterpret_cast<const ulonglong2*>(&s.BH[4 * t]);
        vacc[2 * t] = bb.x; vacc[2 * t + 1] = bb.y;
    }
#pragma unroll
    for (int t = 0; t < 16; t++) {   // i = 2t, 2t+1
        float z0, z1; unpack2(zacc[t], z0, z1);
        u64 zp0 = pack2(z0, z0), zp1 = pack2(z1, z1);
#pragma unroll
        for (int k = 0; k < 8; k++) {
            ulonglong2 w = *reinterpret_cast<const ulonglong2*>(&s.F2[2 * t][4 * k]);
            vacc[2 * k]     = ffma2(zp0, w.x, vacc[2 * k]);
            vacc[2 * k + 1] = ffma2(zp0, w.y, vacc[2 * k + 1]);
        }
#pragma unroll
        for (int k = 0; k < 8; k++) {
            ulonglong2 w = *reinterpret_cast<const ulonglong2*>(&s.F2[2 * t + 1][4 * k]);
            vacc[2 * k]     = ffma2(zp1, w.x, vacc[2 * k]);
            vacc[2 * k + 1] = ffma2(zp1, w.y, vacc[2 * k + 1]);
        }
    }

    // layernorm (mean folded out): var = sum v^2, packed
    u64 varp = 0ull;
#pragma unroll
    for (int t = 0; t < 16; t++) varp = ffma2(vacc[t], vacc[t], varp);
    float v0, v1; unpack2(varp, v0, v1);
    float r = rsqrtf((v0 + v1) * (1.f / 32.f) + 1e-5f);
    u64 rp = pack2(r, r);

    float4* o4 = reinterpret_cast<float4*>(orow);
#pragma unroll
    for (int c = 0; c < 8; c++) {
        u64 y0 = ffma2(fmul2(vacc[2 * c], rp),
                       *reinterpret_cast<const u64*>(&s.G[4 * c]),
                       *reinterpret_cast<const u64*>(&s.BB[4 * c]));
        u64 y1 = ffma2(fmul2(vacc[2 * c + 1], rp),
                       *reinterpret_cast<const u64*>(&s.G[4 * c + 2]),
                       *reinterpret_cast<const u64*>(&s.BB[4 * c + 2]));
        ulonglong2 y; y.x = y0; y.y = y1;
        float4 yf = *reinterpret_cast<float4*>(&y);
        o4[c] = yf;
        fout[(size_t)c * NTOK + n] = yf;
    }
    float4 lab;
    lab.x = (float)row * (1.f / 64.f);
    lab.y = (float)col * (1.f / 64.f);
    lab.z = 0.f; lab.w = 0.f;
    fout[(size_t)8 * NTOK + n] = lab;
}

// ---------------------------------------------------------------------------
// Observation: 10 independent steps, batched over grid.z.
// ---------------------------------------------------------------------------
__global__ void __launch_bounds__(128) obs_kernel(
    float* __restrict__ out,
    const float* __restrict__ lng, const float* __restrict__ lnb)
{
    __shared__ SW s;
    int tid = threadIdx.x;
    stage_weights<128>(s, tid, lng, lnb);
    __syncthreads();

    int z = blockIdx.z;
    const float4* fin = g_ftr + (size_t)z * SLICE;
    float4* fout      = g_ftr + (size_t)(10 + z) * SLICE;

    int n = blockIdx.x * 128 + tid;
    int p = n & 4095;
    int row = p >> 6, col = p & 63;
    int rs = row + (row == 0) - (row == 63);
    int cs = col + (col == 0) - (col == 63);
    int jb = (n >> 12) * 4096;
    int jt[9];
#pragma unroll
    for (int sx = 0; sx < 9; sx++)
        jt[sx] = jb + (rs + sx / 3 - 1) * 64 + (cs + sx % 3 - 1);

    do_token(s, fin, fout, out + ((size_t)z * NTOK + n) * NH, n, jt, row, col);
}

// ---------------------------------------------------------------------------
// Prediction: persistent kernel, 50 sequential steps, one launch.
// 256 blocks x 128 threads (R13 geometry — best measured). All co-resident
// (<=2 blocks/SM, 15.7KB smem, ~170 regs). Block b waits on b+-1 in-batch.
// ---------------------------------------------------------------------------
__global__ void __launch_bounds__(128) pred_kernel(
    float* __restrict__ out,
    const float* __restrict__ lng, const float* __restrict__ lnb)
{
    __shared__ SW s;
    int tid = threadIdx.x;
    stage_weights<128>(s, tid, lng, lnb);
    __syncthreads();

    int b = blockIdx.x;
    int pos = b & 31;                 // block index within its batch (32 blocks/batch)
    int n = b * 128 + tid;
    int p = n & 4095;
    int row = p >> 6, col = p & 63;
    int rs = row + (row == 0) - (row == 63);
    int cs = col + (col == 0) - (col == 63);
    int jb = (n >> 12) * 4096;
    int jt[9];
#pragma unroll
    for (int sx = 0; sx < 9; sx++)
        jt[sx] = jb + (rs + sx / 3 - 1) * 64 + (cs + sx % 3 - 1);

    for (int i = 0; i < 50; i++) {
        const float4* fin = g_ftr + (size_t)(i == 0 ? 19 : 20 + ((i - 1) & 1)) * SLICE;
        float4* fout      = g_ftr + (size_t)(20 + (i & 1)) * SLICE;
        float* orow       = out + ((size_t)(10 + i) * NTOK + n) * NH;

        do_token(s, fin, fout, orow, n, jt, row, col);

        // release all my stores gpu-wide (flushes L1 so next step's reads are
        // fresh), publish progress, wait on the two neighbor strips
        __threadfence();
        __syncthreads();
        if (tid == 0)  atomicExch(&g_flag[b], i + 1);
        if (tid == 0 && pos > 0)
            while (atomicAdd(&g_flag[b - 1], 0) <= i) { __nanosleep(20); }
        if (tid == 32 && pos < 31)
            while (atomicAdd(&g_flag[b + 1], 0) <= i) { __nanosleep(20); }
        __syncthreads();
    }
}

// ---------------------------------------------------------------------------
extern "C" void kernel_launch(void* const* d_in, const int* in_sizes, int n_in,
                              void* d_out, int out_size)
{
    const float* x   = (const float*)d_in[0];
    const float* ipw = (const float*)d_in[1];
    const float* ipb = (const float*)d_in[2];
    const float* opw = (const float*)d_in[3];
    const float* opb = (const float*)d_in[4];
    const float* saw = (const float*)d_in[5];
    const float* sab = (const float*)d_in[6];
    const float* f2w = (const float*)d_in[7];
    const float* f2b = (const float*)d_in[8];
    const float* lng = (const float*)d_in[9];
    const float* lnb = (const float*)d_in[10];
    float* out = (float*)d_out;

    precomp_kernel<<<1, 256>>>(ipw, ipb, opw, opb, saw, sab, f2w, f2b);

    prep_kernel<<<dim3(NTOK / 128, 1, 10), 128>>>(x);

    // Observation: slices 0..9 -> 10..19, output rows 0..9
    obs_kernel<<<dim3(NTOK / 128, 1, 10), 128>>>(out, lng, lnb);

    // Prediction: one persistent launch, 50 sequential steps
    pred_kernel<<<dim3(256, 1, 1), 128>>>(out, lng, lnb);
}